// round 12
// baseline (speedup 1.0000x reference)
#include <cuda_runtime.h>

// ---------------- problem constants ----------------
#define BB   8
#define NN   1024
#define FIN  64
#define CH1  256       // HID
#define CH2  128       // OUT
#define NH   4
#define DD1  64        // CH1/NH
#define DD2  32        // CH2/NH
#define NEG  0.2f

// ---------------- scratch (device globals; no allocation allowed) ----------------
__device__ __align__(16) float g_inv[NN];               // 1/||embed_i||
__device__ unsigned char       g_adjmask[NN * NN];      // mask bytes
__device__ int                 g_deg[NN];
__device__ int                 g_nbr[NN * NN];          // per-row neighbor lists
__device__ __align__(16) float g_Wf[FIN * CH1];         // Wp @ W1
__device__ __align__(16) float g_bf[CH1];               // bp @ W1
__device__ __align__(16) float g_h1[BB * NN * CH1];
__device__ __align__(16) float g_att1[BB * NN * CH1];
__device__ __align__(16) float g_h2[2 * BB * NN * CH2]; // two split-K partials
__device__ float g_src1[BB * NN * NH], g_dst1[BB * NN * NH];

__device__ __forceinline__ float lrelu(float x) { return x > 0.f ? x : NEG * x; }

// ---------------- 1) row norm reciprocals (warp per row) ----------------
__global__ void norm_kernel(const float* __restrict__ embed, float* __restrict__ inv) {
    int w = (blockIdx.x * blockDim.x + threadIdx.x) >> 5;   // row
    int lane = threadIdx.x & 31;
    if (w >= NN) return;
    const float* row = &embed[w * CH1];
    float s = 0.f;
#pragma unroll
    for (int c = 0; c < CH1 / 32; c++) {
        float v = row[c * 32 + lane];
        s = fmaf(v, v, s);
    }
#pragma unroll
    for (int o = 16; o; o >>= 1) s += __shfl_xor_sync(0xffffffffu, s, o);
    if (lane == 0) inv[w] = rsqrtf(s);
}

// ---------------- fused projection weights: Wf = Wp@W1, bf = bp@W1 ----------------
__global__ __launch_bounds__(256)
void wf_kernel(const float* __restrict__ Wp, const float* __restrict__ bp,
               const float* __restrict__ W1,
               float* __restrict__ Wf, float* __restrict__ bf) {
    int r  = blockIdx.x;              // 0..FIN (row FIN = bias row)
    int c0 = blockIdx.y * 16;
    int t  = threadIdx.x;
    int col = t & 15, ks = t >> 4;    // 16 k-slices of 16
    const float* arow = (r < FIN) ? &Wp[r * CH1] : bp;
    float s = 0.f;
    int kbase = ks * 16;
#pragma unroll
    for (int k = 0; k < 16; k++)
        s = fmaf(__ldg(&arow[kbase + k]), __ldg(&W1[(kbase + k) * CH1 + c0 + col]), s);
    __shared__ float red[256];
    red[t] = s;
    __syncthreads();
#pragma unroll
    for (int off = 128; off >= 16; off >>= 1) {
        if (t < off) red[t] += red[t + off];
        __syncthreads();
    }
    if (t < 16) {
        float v = red[t];
        if (r < FIN) Wf[r * CH1 + c0 + t] = v;
        else         bf[c0 + t] = v;
    }
}

// ================= adjacency GEMM: 128x128 tile, 256 threads, mask + mirror ====
// mask[r][c] = (dot(e_r, e_c) * inv_r * inv_c > 0.5); symmetric.
// grid (8,8); skip blocks with bx < by (strictly above-diagonal in col-block
// terms), compute bx >= by and mirror each write. Diagonal double-writes are
// bitwise identical (same k-order dot, product commutes under fmul).
__global__ __launch_bounds__(256)
void adj_kernel(const float* __restrict__ E, const float* __restrict__ inv,
                unsigned char* __restrict__ mask) {
    const int bx = blockIdx.x, by = blockIdx.y;
    if (bx < by) return;
    constexpr int BK = 16;
    __shared__ float As[2][BK][132];   // [k][row] (128 rows)
    __shared__ float Bs[2][BK][132];   // [k][col] (128 cols)

    const int t = threadIdx.x;
    const int row0 = by * 128;
    const int col0 = bx * 128;
    const int ty = t >> 4;            // 8 rows each
    const int tx = t & 15;            // 8 cols each

    float regA[2][4], regB[2][4];
    float acc[8][8];
#pragma unroll
    for (int i = 0; i < 8; i++)
#pragma unroll
        for (int j = 0; j < 8; j++) acc[i][j] = 0.f;

    auto loadA = [&](int k0) {
#pragma unroll
        for (int l = 0; l < 2; l++) {
            int idx = l * 256 + t;
            int r = idx >> 2, c4 = (idx & 3) * 4;
            float4 v = *(const float4*)&E[(row0 + r) * CH1 + k0 + c4];
            regA[l][0] = v.x; regA[l][1] = v.y; regA[l][2] = v.z; regA[l][3] = v.w;
        }
    };
    auto storeA = [&](int buf) {
#pragma unroll
        for (int l = 0; l < 2; l++) {
            int idx = l * 256 + t;
            int r = idx >> 2, c4 = (idx & 3) * 4;
#pragma unroll
            for (int i = 0; i < 4; i++) As[buf][c4 + i][r] = regA[l][i];
        }
    };
    auto loadB = [&](int k0) {
#pragma unroll
        for (int l = 0; l < 2; l++) {
            int idx = l * 256 + t;
            int col = idx >> 2, k4 = (idx & 3) * 4;
            float4 v = *(const float4*)&E[(col0 + col) * CH1 + k0 + k4];
            regB[l][0] = v.x; regB[l][1] = v.y; regB[l][2] = v.z; regB[l][3] = v.w;
        }
    };
    auto storeB = [&](int buf) {
#pragma unroll
        for (int l = 0; l < 2; l++) {
            int idx = l * 256 + t;
            int col = idx >> 2, k4 = (idx & 3) * 4;
#pragma unroll
            for (int i = 0; i < 4; i++) Bs[buf][k4 + i][col] = regB[l][i];
        }
    };
    auto compute = [&](int buf) {
#pragma unroll
        for (int k = 0; k < BK; k++) {
            float a[8], b[8];
            *(float4*)a       = *(const float4*)&As[buf][k][ty * 8];
            *(float4*)(a + 4) = *(const float4*)&As[buf][k][ty * 8 + 4];
            *(float4*)b       = *(const float4*)&Bs[buf][k][tx * 8];
            *(float4*)(b + 4) = *(const float4*)&Bs[buf][k][tx * 8 + 4];
#pragma unroll
            for (int i = 0; i < 8; i++)
#pragma unroll
                for (int j = 0; j < 8; j++)
                    acc[i][j] = fmaf(a[i], b[j], acc[i][j]);
        }
    };

    loadA(0); loadB(0);
    storeA(0); storeB(0);
    __syncthreads();
    int buf = 0;
    for (int k0 = BK; k0 < CH1; k0 += BK) {
        loadA(k0); loadB(k0);
        compute(buf);
        storeA(buf ^ 1); storeB(buf ^ 1);
        __syncthreads();
        buf ^= 1;
    }
    compute(buf);

    float invR[8], invC[8];
#pragma unroll
    for (int i = 0; i < 8; i++) invR[i] = inv[row0 + ty * 8 + i];
#pragma unroll
    for (int j = 0; j < 8; j++) invC[j] = inv[col0 + tx * 8 + j];
#pragma unroll
    for (int i = 0; i < 8; i++) {
        int r = row0 + ty * 8 + i;
#pragma unroll
        for (int j = 0; j < 8; j++) {
            int c = col0 + tx * 8 + j;
            unsigned char v = (acc[i][j] * invR[i] * invC[j] > 0.5f) ? 1 : 0;
            mask[r * NN + c] = v;
            mask[c * NN + r] = v;
        }
    }
}

// ================= gemm5: 128x128 tile, 256 threads, 8x8/thread, split-K ========
template <int K, int SPLIT, bool BIAS, int D>
__launch_bounds__(256)
__global__ void gemm5(const float* __restrict__ A, const float* __restrict__ Bm,
                      const float* __restrict__ bias, float* __restrict__ C,
                      const float* __restrict__ asrc, const float* __restrict__ adst,
                      float* __restrict__ gs, float* __restrict__ gd, int Nc) {
    constexpr int BK = 16;
    constexpr int KS = K / SPLIT;
    __shared__ float As[2][BK][132];
    __shared__ float Bs[2][BK][132];

    const int t = threadIdx.x;
    const int row0 = blockIdx.y * 128;
    const int col0 = blockIdx.x * 128;
    const int kbase = blockIdx.z * KS;
    const int zoff = blockIdx.z * ((int)gridDim.y * 128) * Nc;
    const int ty = t >> 4;
    const int tx = t & 15;

    float regA[2][4], regB[2][4];
    float acc[8][8];
#pragma unroll
    for (int i = 0; i < 8; i++)
#pragma unroll
        for (int j = 0; j < 8; j++) acc[i][j] = 0.f;

    auto loadA = [&](int k0) {
#pragma unroll
        for (int l = 0; l < 2; l++) {
            int idx = l * 256 + t;
            int r = idx >> 2, c4 = (idx & 3) * 4;
            float4 v = *(const float4*)&A[(row0 + r) * K + kbase + k0 + c4];
            regA[l][0] = v.x; regA[l][1] = v.y; regA[l][2] = v.z; regA[l][3] = v.w;
        }
    };
    auto storeA = [&](int buf) {
#pragma unroll
        for (int l = 0; l < 2; l++) {
            int idx = l * 256 + t;
            int r = idx >> 2, c4 = (idx & 3) * 4;
#pragma unroll
            for (int i = 0; i < 4; i++) As[buf][c4 + i][r] = regA[l][i];
        }
    };
    auto loadB = [&](int k0) {
#pragma unroll
        for (int l = 0; l < 2; l++) {
            int idx = l * 256 + t;
            int row = idx >> 5, c4 = (idx & 31) * 4;
            float4 v = *(const float4*)&Bm[(kbase + k0 + row) * Nc + col0 + c4];
            regB[l][0] = v.x; regB[l][1] = v.y; regB[l][2] = v.z; regB[l][3] = v.w;
        }
    };
    auto storeB = [&](int buf) {
#pragma unroll
        for (int l = 0; l < 2; l++) {
            int idx = l * 256 + t;
            int row = idx >> 5, c4 = (idx & 31) * 4;
            *(float4*)&Bs[buf][row][c4] =
                make_float4(regB[l][0], regB[l][1], regB[l][2], regB[l][3]);
        }
    };
    auto compute = [&](int buf) {
#pragma unroll
        for (int k = 0; k < BK; k++) {
            float a[8], b[8];
            *(float4*)a       = *(const float4*)&As[buf][k][ty * 8];
            *(float4*)(a + 4) = *(const float4*)&As[buf][k][ty * 8 + 4];
            *(float4*)b       = *(const float4*)&Bs[buf][k][tx * 8];
            *(float4*)(b + 4) = *(const float4*)&Bs[buf][k][tx * 8 + 4];
#pragma unroll
            for (int i = 0; i < 8; i++)
#pragma unroll
                for (int j = 0; j < 8; j++)
                    acc[i][j] = fmaf(a[i], b[j], acc[i][j]);
        }
    };

    loadA(0); loadB(0);
    storeA(0); storeB(0);
    __syncthreads();
    int buf = 0;
    for (int k0 = BK; k0 < KS; k0 += BK) {
        loadA(k0); loadB(k0);
        compute(buf);
        storeA(buf ^ 1); storeB(buf ^ 1);
        __syncthreads();
        buf ^= 1;
    }
    compute(buf);

    float bv[8];
    if (BIAS) {
#pragma unroll
        for (int j = 0; j < 8; j++) bv[j] = bias[col0 + tx * 8 + j];
    }
#pragma unroll
    for (int i = 0; i < 8; i++) {
#pragma unroll
        for (int j = 0; j < 8; j++) if (BIAS) acc[i][j] += bv[j];
        int r = row0 + ty * 8 + i;
        float4 v0 = make_float4(acc[i][0], acc[i][1], acc[i][2], acc[i][3]);
        float4 v1 = make_float4(acc[i][4], acc[i][5], acc[i][6], acc[i][7]);
        *(float4*)&C[zoff + r * Nc + col0 + tx * 8]     = v0;
        *(float4*)&C[zoff + r * Nc + col0 + tx * 8 + 4] = v1;
    }

    if (D) {   // SPLIT must be 1
        const int gc0 = col0 + tx * 8;
        const int head = gc0 / D;
        float sa[8], sd[8];
#pragma unroll
        for (int j = 0; j < 8; j++) { sa[j] = asrc[gc0 + j]; sd[j] = adst[gc0 + j]; }
        float ps[8], pd[8];
#pragma unroll
        for (int i = 0; i < 8; i++) {
            float s1 = 0.f, s2 = 0.f;
#pragma unroll
            for (int j = 0; j < 8; j++) {
                s1 = fmaf(acc[i][j], sa[j], s1);
                s2 = fmaf(acc[i][j], sd[j], s2);
            }
            ps[i] = s1; pd[i] = s2;
        }
        constexpr int RED = D / 8;
#pragma unroll
        for (int o = RED / 2; o; o >>= 1) {
#pragma unroll
            for (int i = 0; i < 8; i++) {
                ps[i] += __shfl_xor_sync(0xffffffffu, ps[i], o);
                pd[i] += __shfl_xor_sync(0xffffffffu, pd[i], o);
            }
        }
        if ((tx & (RED - 1)) == 0) {
#pragma unroll
            for (int i = 0; i < 8; i++) {
                int r = row0 + ty * 8 + i;
                gs[r * NH + head] = ps[i];
                gd[r * NH + head] = pd[i];
            }
        }
    }
}

// ---------------- 3) compact mask rows -> neighbor lists (warp ballot scan) ------
__global__ void compact_kernel() {
    int gw = (blockIdx.x * blockDim.x + threadIdx.x) >> 5;   // warp id = row
    int lane = threadIdx.x & 31;
    if (gw >= NN) return;
    const uchar4* row = (const uchar4*)&g_adjmask[gw * NN];
    int* dst = &g_nbr[gw * NN];
    int base = 0;
#pragma unroll
    for (int c = 0; c < NN / 128; c++) {
        uchar4 v = row[c * 32 + lane];
        int cnt = (int)v.x + v.y + v.z + v.w;
        int sc = cnt;
#pragma unroll
        for (int o = 1; o < 32; o <<= 1) {
            int n = __shfl_up_sync(0xffffffffu, sc, o);
            if (lane >= o) sc += n;
        }
        int pos = base + sc - cnt;
        int col = (c * 32 + lane) * 4;
        if (v.x) dst[pos++] = col;
        if (v.y) dst[pos++] = col + 1;
        if (v.z) dst[pos++] = col + 2;
        if (v.w) dst[pos++] = col + 3;
        base += __shfl_sync(0xffffffffu, sc, 31);
    }
    if (lane == 0) g_deg[gw] = base;
}

// ---------------- layer-1 attention (coefs precomputed in h1 epilogue) ----------
template <int C, int D, bool RELU>
__global__ void attn_kernel(const float* __restrict__ hin,
                            const float* __restrict__ gsrc,
                            const float* __restrict__ gdst,
                            const float* __restrict__ bias,
                            float* __restrict__ out) {
    int bn = blockIdx.x;
    int b = bn >> 10, i = bn & (NN - 1);
    int t = threadIdx.x;                        // C threads
    int hd = t / D;
    int deg = g_deg[i];
    const int* nb = &g_nbr[i * NN];

    __shared__ float sm[NH], sz[NH];
    int w = t >> 5, lane = t & 31;
    if (w < NH) {
        float adst = gdst[bn * NH + w];
        float mm = -3e38f;
        for (int k = lane; k < deg; k += 32) {
            int j = nb[k];
            float e = lrelu(adst + gsrc[(b * NN + j) * NH + w]);
            mm = fmaxf(mm, e);
        }
#pragma unroll
        for (int o = 16; o; o >>= 1) mm = fmaxf(mm, __shfl_xor_sync(0xffffffffu, mm, o));
        float zz = 0.f;
        for (int k = lane; k < deg; k += 32) {
            int j = nb[k];
            float e = lrelu(adst + gsrc[(b * NN + j) * NH + w]);
            zz += __expf(e - mm);
        }
#pragma unroll
        for (int o = 16; o; o >>= 1) zz += __shfl_xor_sync(0xffffffffu, zz, o);
        if (lane == 0) { sm[w] = mm; sz[w] = zz; }
    }
    __syncthreads();

    float adst = gdst[bn * NH + hd];
    float mh = sm[hd];
    float invZ = 1.0f / sz[hd];
    float acc = 0.f;
    for (int k = 0; k < deg; k++) {
        int j = nb[k];
        float e = lrelu(adst + gsrc[(b * NN + j) * NH + hd]);
        float wt = __expf(e - mh) * invZ;
        acc = fmaf(wt, hin[(b * NN + j) * C + t], acc);
    }
    float o = acc + bias[t];
    out[bn * C + t] = RELU ? fmaxf(o, 0.f) : o;
}

// ---------------- layer-2 attention: sums split-K partials, computes own coefs ---
__global__ __launch_bounds__(128)
void attn2_kernel(const float* __restrict__ P,
                  const float* __restrict__ asrc, const float* __restrict__ adst,
                  const float* __restrict__ bias, float* __restrict__ out) {
    constexpr int PSZ = BB * NN * CH2;
    int bn = blockIdx.x;
    int b = bn >> 10, i = bn & (NN - 1);
    int t = threadIdx.x;               // 0..127 = output column
    int w = t >> 5, lane = t & 31;     // warp = head (NH = 4 = CH2/32)
    int deg = g_deg[i];
    const int* nb = &g_nbr[i * NN];

    __shared__ float es[NH][NN];
    __shared__ float sdst[NH], sinvZ[NH];

    {
        int base = (b * NN + i) * CH2 + t;
        float hv = P[base] + P[PSZ + base];
        float s = hv * adst[t];
#pragma unroll
        for (int o = 16; o; o >>= 1) s += __shfl_xor_sync(0xffffffffu, s, o);
        if (lane == 0) sdst[w] = s;
    }
    __syncthreads();

    {
        float ad = sdst[w];
        float av = asrc[w * 32 + lane];
        for (int k = 0; k < deg; k++) {
            int j = nb[k];
            int base = (b * NN + j) * CH2 + w * 32 + lane;
            float hj = P[base] + P[PSZ + base];
            float s = hj * av;
#pragma unroll
            for (int o = 16; o; o >>= 1) s += __shfl_xor_sync(0xffffffffu, s, o);
            if (lane == 0) es[w][k] = lrelu(ad + s);
        }
        __syncwarp();
        float mm = -3e38f;
        for (int k = lane; k < deg; k += 32) mm = fmaxf(mm, es[w][k]);
#pragma unroll
        for (int o = 16; o; o >>= 1) mm = fmaxf(mm, __shfl_xor_sync(0xffffffffu, mm, o));
        float zz = 0.f;
        for (int k = lane; k < deg; k += 32) {
            float e = __expf(es[w][k] - mm);
            es[w][k] = e;
            zz += e;
        }
#pragma unroll
        for (int o = 16; o; o >>= 1) zz += __shfl_xor_sync(0xffffffffu, zz, o);
        if (lane == 0) sinvZ[w] = 1.0f / zz;
    }
    __syncthreads();

    float invZ = sinvZ[w];
    float acc = 0.f;
    for (int k = 0; k < deg; k++) {
        int j = nb[k];
        int base = (b * NN + j) * CH2 + t;
        acc = fmaf(es[w][k], P[base] + P[PSZ + base], acc);
    }
    out[bn * CH2 + t] = acc * invZ + bias[t];
}

// ---------------- launcher (serial) ----------------
extern "C" void kernel_launch(void* const* d_in, const int* in_sizes, int n_in,
                              void* d_out, int out_size) {
    const float* x      = (const float*)d_in[0];
    const float* embed  = (const float*)d_in[1];
    const float* Wp     = (const float*)d_in[2];
    const float* bp     = (const float*)d_in[3];
    const float* W1     = (const float*)d_in[4];
    const float* a_src1 = (const float*)d_in[5];
    const float* a_dst1 = (const float*)d_in[6];
    const float* b1     = (const float*)d_in[7];
    const float* W2     = (const float*)d_in[8];
    const float* a_src2 = (const float*)d_in[9];
    const float* a_dst2 = (const float*)d_in[10];
    const float* b2     = (const float*)d_in[11];
    float* out = (float*)d_out;

    float *p_inv, *p_Wf, *p_bf, *p_h1, *p_att1, *p_h2, *p_s1, *p_d1;
    unsigned char* p_mask;
    cudaGetSymbolAddress((void**)&p_inv,  g_inv);
    cudaGetSymbolAddress((void**)&p_mask, g_adjmask);
    cudaGetSymbolAddress((void**)&p_Wf,   g_Wf);
    cudaGetSymbolAddress((void**)&p_bf,   g_bf);
    cudaGetSymbolAddress((void**)&p_h1,   g_h1);
    cudaGetSymbolAddress((void**)&p_att1, g_att1);
    cudaGetSymbolAddress((void**)&p_h2,   g_h2);
    cudaGetSymbolAddress((void**)&p_s1,   g_src1);
    cudaGetSymbolAddress((void**)&p_d1,   g_dst1);

    // adjacency pipeline (batch-independent)
    norm_kernel<<<NN / 8, 256>>>(embed, p_inv);
    adj_kernel<<<dim3(NN / 128, NN / 128), 256>>>(embed, p_inv, p_mask);
    compact_kernel<<<NN / 8, 256>>>();

    // fused projection: Wf = Wp @ W1 (+ bf = bp @ W1 as row 64)
    wf_kernel<<<dim3(FIN + 1, CH1 / 16), 256>>>(Wp, bp, W1, p_Wf, p_bf);

    // h1 = x @ Wf + bf   [8192,64]@[64,256], attn-coef epilogue (D=64)
    gemm5<FIN, 1, true, DD1><<<dim3(CH1 / 128, BB * NN / 128, 1), 256>>>(
        x, p_Wf, p_bf, p_h1, a_src1, a_dst1, p_s1, p_d1, CH1);
    // attention layer 1 (relu epilogue, +b1)
    attn_kernel<CH1, DD1, true><<<BB * NN, CH1>>>(p_h1, p_s1, p_d1, b1, p_att1);

    // h2 partials = att1 @ W2 (split-K x2)   [8192,256]@[256,128]
    gemm5<CH1, 2, false, 0><<<dim3(CH2 / 128, BB * NN / 128, 2), 256>>>(
        p_att1, W2, nullptr, p_h2, nullptr, nullptr, nullptr, nullptr, CH2);
    // attention layer 2: sums partials, computes coefs, (+b2) -> output
    attn2_kernel<<<BB * NN, CH2>>>(p_h2, a_src2, a_dst2, b2, out);
}

// round 13
// speedup vs baseline: 1.1663x; 1.1663x over previous
#include <cuda_runtime.h>

// ---------------- problem constants ----------------
#define BB   8
#define NN   1024
#define FIN  64
#define CH1  256       // HID
#define CH2  128       // OUT
#define NH   4
#define DD1  64        // CH1/NH
#define DD2  32        // CH2/NH
#define NEG  0.2f

// ---------------- scratch (device globals; no allocation allowed) ----------------
__device__ __align__(16) float g_inv[NN];               // 1/||embed_i||
__device__ unsigned char       g_adjmask[NN * NN];      // mask bytes
__device__ int                 g_deg[NN];
__device__ int                 g_nbr[NN * NN];          // per-row neighbor lists
__device__ __align__(16) float g_Wf[FIN * CH1];         // Wp @ W1
__device__ __align__(16) float g_bf[CH1];               // bp @ W1
__device__ __align__(16) float g_h1[BB * NN * CH1];
__device__ __align__(16) float g_att1[BB * NN * CH1];
__device__ __align__(16) float g_h2[2 * BB * NN * CH2]; // two split-K partials
__device__ float g_src1[BB * NN * NH], g_dst1[BB * NN * NH];

__device__ __forceinline__ float lrelu(float x) { return x > 0.f ? x : NEG * x; }

// ---------------- pre_kernel: norm (blocks 0..127) + wf (blocks 128..1167) ------
// norm: warp per row -> g_inv. wf: Wf = Wp@W1 rowwise split-K x16 (row FIN = bias).
__global__ __launch_bounds__(256)
void pre_kernel(const float* __restrict__ embed, float* __restrict__ inv,
                const float* __restrict__ Wp, const float* __restrict__ bp,
                const float* __restrict__ W1,
                float* __restrict__ Wf, float* __restrict__ bf) {
    int bx = blockIdx.x;
    int t = threadIdx.x;
    if (bx < 128) {
        // ---- norm path: 8 rows per block (warp per row) ----
        int w = (bx * 256 + t) >> 5;
        int lane = t & 31;
        const float* row = &embed[w * CH1];
        float s = 0.f;
#pragma unroll
        for (int c = 0; c < CH1 / 32; c++) {
            float v = row[c * 32 + lane];
            s = fmaf(v, v, s);
        }
#pragma unroll
        for (int o = 16; o; o >>= 1) s += __shfl_xor_sync(0xffffffffu, s, o);
        if (lane == 0) inv[w] = rsqrtf(s);
        return;
    }
    // ---- wf path ----
    int idx = bx - 128;               // 0..1039
    int r  = idx >> 4;                // 0..64 (row FIN = bias row)
    int c0 = (idx & 15) * 16;
    int col = t & 15, ks = t >> 4;    // 16 k-slices of 16
    const float* arow = (r < FIN) ? &Wp[r * CH1] : bp;
    float s = 0.f;
    int kbase = ks * 16;
#pragma unroll
    for (int k = 0; k < 16; k++)
        s = fmaf(__ldg(&arow[kbase + k]), __ldg(&W1[(kbase + k) * CH1 + c0 + col]), s);
    __shared__ float red[256];
    red[t] = s;
    __syncthreads();
#pragma unroll
    for (int off = 128; off >= 16; off >>= 1) {
        if (t < off) red[t] += red[t + off];
        __syncthreads();
    }
    if (t < 16) {
        float v = red[t];
        if (r < FIN) Wf[r * CH1 + c0 + t] = v;
        else         bf[c0 + t] = v;
    }
}

// ================= adjacency GEMM: 64x128 TRANSB tile, mask out + mirror ========
// (R11 config: 128 threads, 92 active blocks — proven fastest; 128x128/256thr
//  collapsed the grid to 36 blocks and regressed.)
__global__ __launch_bounds__(128)
void adj_kernel(const float* __restrict__ E, const float* __restrict__ inv,
                unsigned char* __restrict__ mask) {
    const int cx = blockIdx.x, ry = blockIdx.y;
    if (ry >= 2 * cx + 2) return;     // entirely below diagonal -> covered by mirror
    constexpr int BK = 16;
    __shared__ float As[2][BK][68];
    __shared__ float Bs[2][BK][132];

    const int t = threadIdx.x;
    const int row0 = ry * 64;
    const int col0 = cx * 128;
    const int ty = t >> 4;
    const int tx = t & 15;

    float regA[2][4], regB[4][4];
    float acc[8][8];
#pragma unroll
    for (int i = 0; i < 8; i++)
#pragma unroll
        for (int j = 0; j < 8; j++) acc[i][j] = 0.f;

    auto loadA = [&](int k0) {
#pragma unroll
        for (int l = 0; l < 2; l++) {
            int idx = l * 128 + t;
            int r = idx >> 2, c4 = (idx & 3) * 4;
            float4 v = *(const float4*)&E[(row0 + r) * CH1 + k0 + c4];
            regA[l][0] = v.x; regA[l][1] = v.y; regA[l][2] = v.z; regA[l][3] = v.w;
        }
    };
    auto storeA = [&](int buf) {
#pragma unroll
        for (int l = 0; l < 2; l++) {
            int idx = l * 128 + t;
            int r = idx >> 2, c4 = (idx & 3) * 4;
#pragma unroll
            for (int i = 0; i < 4; i++) As[buf][c4 + i][r] = regA[l][i];
        }
    };
    auto loadB = [&](int k0) {
#pragma unroll
        for (int l = 0; l < 4; l++) {
            int idx = l * 128 + t;
            int col = idx >> 2, k4 = (idx & 3) * 4;
            float4 v = *(const float4*)&E[(col0 + col) * CH1 + k0 + k4];
            regB[l][0] = v.x; regB[l][1] = v.y; regB[l][2] = v.z; regB[l][3] = v.w;
        }
    };
    auto storeB = [&](int buf) {
#pragma unroll
        for (int l = 0; l < 4; l++) {
            int idx = l * 128 + t;
            int col = idx >> 2, k4 = (idx & 3) * 4;
#pragma unroll
            for (int i = 0; i < 4; i++) Bs[buf][k4 + i][col] = regB[l][i];
        }
    };
    auto compute = [&](int buf) {
#pragma unroll
        for (int k = 0; k < BK; k++) {
            float a[8], b[8];
            *(float4*)a       = *(const float4*)&As[buf][k][ty * 8];
            *(float4*)(a + 4) = *(const float4*)&As[buf][k][ty * 8 + 4];
            *(float4*)b       = *(const float4*)&Bs[buf][k][tx * 8];
            *(float4*)(b + 4) = *(const float4*)&Bs[buf][k][tx * 8 + 4];
#pragma unroll
            for (int i = 0; i < 8; i++)
#pragma unroll
                for (int j = 0; j < 8; j++)
                    acc[i][j] = fmaf(a[i], b[j], acc[i][j]);
        }
    };

    loadA(0); loadB(0);
    storeA(0); storeB(0);
    __syncthreads();
    int buf = 0;
    for (int k0 = BK; k0 < CH1; k0 += BK) {
        loadA(k0); loadB(k0);
        compute(buf);
        storeA(buf ^ 1); storeB(buf ^ 1);
        __syncthreads();
        buf ^= 1;
    }
    compute(buf);

    float invR[8], invC[8];
#pragma unroll
    for (int i = 0; i < 8; i++) invR[i] = inv[row0 + ty * 8 + i];
#pragma unroll
    for (int j = 0; j < 8; j++) invC[j] = inv[col0 + tx * 8 + j];
#pragma unroll
    for (int i = 0; i < 8; i++) {
        int r = row0 + ty * 8 + i;
#pragma unroll
        for (int j = 0; j < 8; j++) {
            int c = col0 + tx * 8 + j;
            unsigned char v = (acc[i][j] * invR[i] * invC[j] > 0.5f) ? 1 : 0;
            mask[r * NN + c] = v;
            mask[c * NN + r] = v;
        }
    }
}

// ================= gemm5: 128x128 tile, 256 threads, 8x8/thread, split-K ========
template <int K, int SPLIT, bool BIAS, int D>
__launch_bounds__(256)
__global__ void gemm5(const float* __restrict__ A, const float* __restrict__ Bm,
                      const float* __restrict__ bias, float* __restrict__ C,
                      const float* __restrict__ asrc, const float* __restrict__ adst,
                      float* __restrict__ gs, float* __restrict__ gd, int Nc) {
    constexpr int BK = 16;
    constexpr int KS = K / SPLIT;
    __shared__ float As[2][BK][132];
    __shared__ float Bs[2][BK][132];

    const int t = threadIdx.x;
    const int row0 = blockIdx.y * 128;
    const int col0 = blockIdx.x * 128;
    const int kbase = blockIdx.z * KS;
    const int zoff = blockIdx.z * ((int)gridDim.y * 128) * Nc;
    const int ty = t >> 4;
    const int tx = t & 15;

    float regA[2][4], regB[2][4];
    float acc[8][8];
#pragma unroll
    for (int i = 0; i < 8; i++)
#pragma unroll
        for (int j = 0; j < 8; j++) acc[i][j] = 0.f;

    auto loadA = [&](int k0) {
#pragma unroll
        for (int l = 0; l < 2; l++) {
            int idx = l * 256 + t;
            int r = idx >> 2, c4 = (idx & 3) * 4;
            float4 v = *(const float4*)&A[(row0 + r) * K + kbase + k0 + c4];
            regA[l][0] = v.x; regA[l][1] = v.y; regA[l][2] = v.z; regA[l][3] = v.w;
        }
    };
    auto storeA = [&](int buf) {
#pragma unroll
        for (int l = 0; l < 2; l++) {
            int idx = l * 256 + t;
            int r = idx >> 2, c4 = (idx & 3) * 4;
#pragma unroll
            for (int i = 0; i < 4; i++) As[buf][c4 + i][r] = regA[l][i];
        }
    };
    auto loadB = [&](int k0) {
#pragma unroll
        for (int l = 0; l < 2; l++) {
            int idx = l * 256 + t;
            int row = idx >> 5, c4 = (idx & 31) * 4;
            float4 v = *(const float4*)&Bm[(kbase + k0 + row) * Nc + col0 + c4];
            regB[l][0] = v.x; regB[l][1] = v.y; regB[l][2] = v.z; regB[l][3] = v.w;
        }
    };
    auto storeB = [&](int buf) {
#pragma unroll
        for (int l = 0; l < 2; l++) {
            int idx = l * 256 + t;
            int row = idx >> 5, c4 = (idx & 31) * 4;
            *(float4*)&Bs[buf][row][c4] =
                make_float4(regB[l][0], regB[l][1], regB[l][2], regB[l][3]);
        }
    };
    auto compute = [&](int buf) {
#pragma unroll
        for (int k = 0; k < BK; k++) {
            float a[8], b[8];
            *(float4*)a       = *(const float4*)&As[buf][k][ty * 8];
            *(float4*)(a + 4) = *(const float4*)&As[buf][k][ty * 8 + 4];
            *(float4*)b       = *(const float4*)&Bs[buf][k][tx * 8];
            *(float4*)(b + 4) = *(const float4*)&Bs[buf][k][tx * 8 + 4];
#pragma unroll
            for (int i = 0; i < 8; i++)
#pragma unroll
                for (int j = 0; j < 8; j++)
                    acc[i][j] = fmaf(a[i], b[j], acc[i][j]);
        }
    };

    loadA(0); loadB(0);
    storeA(0); storeB(0);
    __syncthreads();
    int buf = 0;
    for (int k0 = BK; k0 < KS; k0 += BK) {
        loadA(k0); loadB(k0);
        compute(buf);
        storeA(buf ^ 1); storeB(buf ^ 1);
        __syncthreads();
        buf ^= 1;
    }
    compute(buf);

    float bv[8];
    if (BIAS) {
#pragma unroll
        for (int j = 0; j < 8; j++) bv[j] = bias[col0 + tx * 8 + j];
    }
#pragma unroll
    for (int i = 0; i < 8; i++) {
#pragma unroll
        for (int j = 0; j < 8; j++) if (BIAS) acc[i][j] += bv[j];
        int r = row0 + ty * 8 + i;
        float4 v0 = make_float4(acc[i][0], acc[i][1], acc[i][2], acc[i][3]);
        float4 v1 = make_float4(acc[i][4], acc[i][5], acc[i][6], acc[i][7]);
        *(float4*)&C[zoff + r * Nc + col0 + tx * 8]     = v0;
        *(float4*)&C[zoff + r * Nc + col0 + tx * 8 + 4] = v1;
    }

    if (D) {   // SPLIT must be 1
        const int gc0 = col0 + tx * 8;
        const int head = gc0 / D;
        float sa[8], sd[8];
#pragma unroll
        for (int j = 0; j < 8; j++) { sa[j] = asrc[gc0 + j]; sd[j] = adst[gc0 + j]; }
        float ps[8], pd[8];
#pragma unroll
        for (int i = 0; i < 8; i++) {
            float s1 = 0.f, s2 = 0.f;
#pragma unroll
            for (int j = 0; j < 8; j++) {
                s1 = fmaf(acc[i][j], sa[j], s1);
                s2 = fmaf(acc[i][j], sd[j], s2);
            }
            ps[i] = s1; pd[i] = s2;
        }
        constexpr int RED = D / 8;
#pragma unroll
        for (int o = RED / 2; o; o >>= 1) {
#pragma unroll
            for (int i = 0; i < 8; i++) {
                ps[i] += __shfl_xor_sync(0xffffffffu, ps[i], o);
                pd[i] += __shfl_xor_sync(0xffffffffu, pd[i], o);
            }
        }
        if ((tx & (RED - 1)) == 0) {
#pragma unroll
            for (int i = 0; i < 8; i++) {
                int r = row0 + ty * 8 + i;
                gs[r * NH + head] = ps[i];
                gd[r * NH + head] = pd[i];
            }
        }
    }
}

// ---------------- compact mask rows -> neighbor lists (warp ballot scan) ------
__global__ void compact_kernel() {
    int gw = (blockIdx.x * blockDim.x + threadIdx.x) >> 5;   // warp id = row
    int lane = threadIdx.x & 31;
    if (gw >= NN) return;
    const uchar4* row = (const uchar4*)&g_adjmask[gw * NN];
    int* dst = &g_nbr[gw * NN];
    int base = 0;
#pragma unroll
    for (int c = 0; c < NN / 128; c++) {
        uchar4 v = row[c * 32 + lane];
        int cnt = (int)v.x + v.y + v.z + v.w;
        int sc = cnt;
#pragma unroll
        for (int o = 1; o < 32; o <<= 1) {
            int n = __shfl_up_sync(0xffffffffu, sc, o);
            if (lane >= o) sc += n;
        }
        int pos = base + sc - cnt;
        int col = (c * 32 + lane) * 4;
        if (v.x) dst[pos++] = col;
        if (v.y) dst[pos++] = col + 1;
        if (v.z) dst[pos++] = col + 2;
        if (v.w) dst[pos++] = col + 3;
        base += __shfl_sync(0xffffffffu, sc, 31);
    }
    if (lane == 0) g_deg[gw] = base;
}

// ---------------- layer-1 attention, 4 rows per block ----------------
template <int C, int D, bool RELU, int ROWS>
__global__ void attn_kernel(const float* __restrict__ hin,
                            const float* __restrict__ gsrc,
                            const float* __restrict__ gdst,
                            const float* __restrict__ bias,
                            float* __restrict__ out) {
    int t = threadIdx.x;                        // C threads
    int hd = t / D;
    int w = t >> 5, lane = t & 31;
    float bb = bias[t];
    __shared__ float sm[NH], sz[NH];

    for (int rr = 0; rr < ROWS; rr++) {
        int bn = blockIdx.x * ROWS + rr;
        int b = bn >> 10, i = bn & (NN - 1);
        int deg = g_deg[i];
        const int* nb = &g_nbr[i * NN];

        if (w < NH) {
            float adst = gdst[bn * NH + w];
            float mm = -3e38f;
            for (int k = lane; k < deg; k += 32) {
                int j = nb[k];
                float e = lrelu(adst + gsrc[(b * NN + j) * NH + w]);
                mm = fmaxf(mm, e);
            }
#pragma unroll
            for (int o = 16; o; o >>= 1) mm = fmaxf(mm, __shfl_xor_sync(0xffffffffu, mm, o));
            float zz = 0.f;
            for (int k = lane; k < deg; k += 32) {
                int j = nb[k];
                float e = lrelu(adst + gsrc[(b * NN + j) * NH + w]);
                zz += __expf(e - mm);
            }
#pragma unroll
            for (int o = 16; o; o >>= 1) zz += __shfl_xor_sync(0xffffffffu, zz, o);
            if (lane == 0) { sm[w] = mm; sz[w] = zz; }
        }
        __syncthreads();

        float adst = gdst[bn * NH + hd];
        float mh = sm[hd];
        float invZ = 1.0f / sz[hd];
        float acc = 0.f;
        for (int k = 0; k < deg; k++) {
            int j = nb[k];
            float e = lrelu(adst + gsrc[(b * NN + j) * NH + hd]);
            float wt = __expf(e - mh) * invZ;
            acc = fmaf(wt, hin[(b * NN + j) * C + t], acc);
        }
        float o = acc + bb;
        out[bn * C + t] = RELU ? fmaxf(o, 0.f) : o;
        __syncthreads();
    }
}

// ---------------- layer-2 attention: sums split-K partials, computes own coefs ---
__global__ __launch_bounds__(128)
void attn2_kernel(const float* __restrict__ P,
                  const float* __restrict__ asrc, const float* __restrict__ adst,
                  const float* __restrict__ bias, float* __restrict__ out) {
    constexpr int PSZ = BB * NN * CH2;
    int bn = blockIdx.x;
    int b = bn >> 10, i = bn & (NN - 1);
    int t = threadIdx.x;               // 0..127 = output column
    int w = t >> 5, lane = t & 31;     // warp = head
    int deg = g_deg[i];
    const int* nb = &g_nbr[i * NN];

    __shared__ float es[NH][NN];
    __shared__ float sdst[NH], sinvZ[NH];

    {
        int base = (b * NN + i) * CH2 + t;
        float hv = P[base] + P[PSZ + base];
        float s = hv * adst[t];
#pragma unroll
        for (int o = 16; o; o >>= 1) s += __shfl_xor_sync(0xffffffffu, s, o);
        if (lane == 0) sdst[w] = s;
    }
    __syncthreads();

    {
        float ad = sdst[w];
        float av = asrc[w * 32 + lane];
        for (int k = 0; k < deg; k++) {
            int j = nb[k];
            int base = (b * NN + j) * CH2 + w * 32 + lane;
            float hj = P[base] + P[PSZ + base];
            float s = hj * av;
#pragma unroll
            for (int o = 16; o; o >>= 1) s += __shfl_xor_sync(0xffffffffu, s, o);
            if (lane == 0) es[w][k] = lrelu(ad + s);
        }
        __syncwarp();
        float mm = -3e38f;
        for (int k = lane; k < deg; k += 32) mm = fmaxf(mm, es[w][k]);
#pragma unroll
        for (int o = 16; o; o >>= 1) mm = fmaxf(mm, __shfl_xor_sync(0xffffffffu, mm, o));
        float zz = 0.f;
        for (int k = lane; k < deg; k += 32) {
            float e = __expf(es[w][k] - mm);
            es[w][k] = e;
            zz += e;
        }
#pragma unroll
        for (int o = 16; o; o >>= 1) zz += __shfl_xor_sync(0xffffffffu, zz, o);
        if (lane == 0) sinvZ[w] = 1.0f / zz;
    }
    __syncthreads();

    float invZ = sinvZ[w];
    float acc = 0.f;
    for (int k = 0; k < deg; k++) {
        int j = nb[k];
        int base = (b * NN + j) * CH2 + t;
        acc = fmaf(es[w][k], P[base] + P[PSZ + base], acc);
    }
    out[bn * CH2 + t] = acc * invZ + bias[t];
}

// ---------------- launcher (serial) ----------------
extern "C" void kernel_launch(void* const* d_in, const int* in_sizes, int n_in,
                              void* d_out, int out_size) {
    const float* x      = (const float*)d_in[0];
    const float* embed  = (const float*)d_in[1];
    const float* Wp     = (const float*)d_in[2];
    const float* bp     = (const float*)d_in[3];
    const float* W1     = (const float*)d_in[4];
    const float* a_src1 = (const float*)d_in[5];
    const float* a_dst1 = (const float*)d_in[6];
    const float* b1     = (const float*)d_in[7];
    const float* W2     = (const float*)d_in[8];
    const float* a_src2 = (const float*)d_in[9];
    const float* a_dst2 = (const float*)d_in[10];
    const float* b2     = (const float*)d_in[11];
    float* out = (float*)d_out;

    float *p_inv, *p_Wf, *p_bf, *p_h1, *p_att1, *p_h2, *p_s1, *p_d1;
    unsigned char* p_mask;
    cudaGetSymbolAddress((void**)&p_inv,  g_inv);
    cudaGetSymbolAddress((void**)&p_mask, g_adjmask);
    cudaGetSymbolAddress((void**)&p_Wf,   g_Wf);
    cudaGetSymbolAddress((void**)&p_bf,   g_bf);
    cudaGetSymbolAddress((void**)&p_h1,   g_h1);
    cudaGetSymbolAddress((void**)&p_att1, g_att1);
    cudaGetSymbolAddress((void**)&p_h2,   g_h2);
    cudaGetSymbolAddress((void**)&p_s1,   g_src1);
    cudaGetSymbolAddress((void**)&p_d1,   g_dst1);

    // preprocessing: norms + fused projection weights, one launch
    pre_kernel<<<128 + (FIN + 1) * (CH1 / 16), 256>>>(embed, p_inv, Wp, bp, W1, p_Wf, p_bf);

    // adjacency mask (64x128 tiles, 92 active blocks) + neighbor lists
    adj_kernel<<<dim3(NN / 128, NN / 64), 128>>>(embed, p_inv, p_mask);
    compact_kernel<<<NN / 8, 256>>>();

    // h1 = x @ Wf + bf   [8192,64]@[64,256], attn-coef epilogue (D=64)
    gemm5<FIN, 1, true, DD1><<<dim3(CH1 / 128, BB * NN / 128, 1), 256>>>(
        x, p_Wf, p_bf, p_h1, a_src1, a_dst1, p_s1, p_d1, CH1);
    // attention layer 1 (relu epilogue, +b1), 4 rows per block
    attn_kernel<CH1, DD1, true, 4><<<BB * NN / 4, CH1>>>(p_h1, p_s1, p_d1, b1, p_att1);

    // h2 partials = att1 @ W2 (split-K x2)   [8192,256]@[256,128]
    gemm5<CH1, 2, false, 0><<<dim3(CH2 / 128, BB * NN / 128, 2), 256>>>(
        p_att1, W2, nullptr, p_h2, nullptr, nullptr, nullptr, nullptr, CH2);
    // attention layer 2: sums partials, computes coefs, (+b2) -> output
    attn2_kernel<<<BB * NN, CH2>>>(p_h2, a_src2, a_dst2, b2, out);
}